// round 8
// baseline (speedup 1.0000x reference)
#include <cuda_runtime.h>
#include <stdint.h>

// Haar DWT level-1 on x: (B=32, L=4096, F=512) fp32.
// out[b, p, f]      = (x[b,2p,f] + x[b,2p+1,f]) / sqrt2   (p in [0,2048))
// out[b, 2048+p, f] = (x[b,2p,f] - x[b,2p+1,f]) / sqrt2
//
// R3 memory pattern (lane = f4 stride-1, MLP=4 via two distant pairs,
// PLAIN loads/stores) in a single-wave persistent grid-stride loop.
// This isolates "persistence" from the .cs-store regression R4 conflated it with.

#define B 32
#define L 4096
#define F 512
#define HALF_L (L / 2)
#define F4 (F / 4)                        // 128 float4 per row
#define PQ (HALF_L / 2)                   // 1024 pair-indices
#define TOTAL_T (B * PQ * F4)             // 4,194,304 work items
#define ROW F4
#define DOFF (HALF_L * F4)

#define NUM_SMS 148
#define CTAS_PER_SM 8
#define NBLOCKS (NUM_SMS * CTAS_PER_SM)   // 1184
#define NTHREADS 256
#define STRIDE (NBLOCKS * NTHREADS)       // 303,104

__global__ __launch_bounds__(NTHREADS) void haar_dwt_kernel(
    const float4* __restrict__ x, float4* __restrict__ out)
{
    const float s = 0.70710678118654752440f;

    for (unsigned t = blockIdx.x * NTHREADS + threadIdx.x; t < TOTAL_T; t += STRIDE)
    {
        unsigned f4 = t & (F4 - 1);       // lane-contiguous
        unsigned p  = (t >> 7) & (PQ - 1);
        unsigned b  = t >> 17;

        unsigned base_b = b * (L * F4);

        unsigned in0 = base_b + (2u * p) * ROW + f4;
        unsigned in1 = in0 + 2u * PQ * ROW;

        // 4 independent coalesced loads batched up front
        float4 a0 = x[in0];
        float4 a1 = x[in0 + ROW];
        float4 b0 = x[in1];
        float4 b1 = x[in1 + ROW];

        float4 ca0, cd0, ca1, cd1;
        ca0.x = (a0.x + a1.x) * s;  cd0.x = (a0.x - a1.x) * s;
        ca0.y = (a0.y + a1.y) * s;  cd0.y = (a0.y - a1.y) * s;
        ca0.z = (a0.z + a1.z) * s;  cd0.z = (a0.z - a1.z) * s;
        ca0.w = (a0.w + a1.w) * s;  cd0.w = (a0.w - a1.w) * s;
        ca1.x = (b0.x + b1.x) * s;  cd1.x = (b0.x - b1.x) * s;
        ca1.y = (b0.y + b1.y) * s;  cd1.y = (b0.y - b1.y) * s;
        ca1.z = (b0.z + b1.z) * s;  cd1.z = (b0.z - b1.z) * s;
        ca1.w = (b0.w + b1.w) * s;  cd1.w = (b0.w - b1.w) * s;

        unsigned outA0 = base_b + p * ROW + f4;
        unsigned outA1 = outA0 + PQ * ROW;

        out[outA0]        = ca0;
        out[outA1]        = ca1;
        out[outA0 + DOFF] = cd0;
        out[outA1 + DOFF] = cd1;
    }
}

extern "C" void kernel_launch(void* const* d_in, const int* in_sizes, int n_in,
                              void* d_out, int out_size)
{
    const float4* x = (const float4*)d_in[0];
    float4* out = (float4*)d_out;

    haar_dwt_kernel<<<NBLOCKS, NTHREADS>>>(x, out);
}

// round 9
// speedup vs baseline: 1.1291x; 1.1291x over previous
#include <cuda_runtime.h>
#include <stdint.h>

// Haar DWT level-1 on x: (B=32, L=4096, F=512) fp32.
// out[b, p, f]      = (x[b,2p,f] + x[b,2p+1,f]) / sqrt2   (p in [0,2048))
// out[b, 2048+p, f] = (x[b,2p,f] - x[b,2p+1,f]) / sqrt2
//
// FINAL (= R3, best of 8 measured variants, 74.59us kernel, DRAM 81.5%):
//  - lane = f4, stride-1 float4 within warp -> every LDG.128/STG.128 is a
//    512B lane-contiguous warp transaction (coalescing is the binding factor)
//  - MLP=4 per thread via two pairs at distant p (p and p+1024)
//  - PLAIN loads and stores (all cache hints measured harmful/neutral)
//  - multi-wave launch (persistent grid-stride measured -5% DRAM duty)

#define B 32
#define L 4096
#define F 512
#define HALF_L (L / 2)
#define F4 (F / 4)                        // 128 float4 per row
#define PQ (HALF_L / 2)                   // 1024 pair-indices per thread-group
#define TOTAL_T (B * PQ * F4)             // 4,194,304 threads

__global__ __launch_bounds__(256) void haar_dwt_kernel(
    const float4* __restrict__ x, float4* __restrict__ out)
{
    int t = blockIdx.x * blockDim.x + threadIdx.x;

    int f4 = t & (F4 - 1);                // 0..127 (lane-contiguous)
    int p  = (t >> 7) & (PQ - 1);         // 0..1023
    int b  = t >> 17;                     // 0..31

    long row = (long)F4;
    long base_b = (long)b * (L * F4);

    long in0 = base_b + (long)(2 * p) * row + f4;
    long in1 = base_b + (long)(2 * (p + PQ)) * row + f4;

    // 4 independent coalesced loads batched up front
    float4 a0 = x[in0];
    float4 a1 = x[in0 + row];
    float4 b0 = x[in1];
    float4 b1 = x[in1 + row];

    const float s = 0.70710678118654752440f;
    float4 ca0, cd0, ca1, cd1;
    ca0.x = (a0.x + a1.x) * s;  cd0.x = (a0.x - a1.x) * s;
    ca0.y = (a0.y + a1.y) * s;  cd0.y = (a0.y - a1.y) * s;
    ca0.z = (a0.z + a1.z) * s;  cd0.z = (a0.z - a1.z) * s;
    ca0.w = (a0.w + a1.w) * s;  cd0.w = (a0.w - a1.w) * s;
    ca1.x = (b0.x + b1.x) * s;  cd1.x = (b0.x - b1.x) * s;
    ca1.y = (b0.y + b1.y) * s;  cd1.y = (b0.y - b1.y) * s;
    ca1.z = (b0.z + b1.z) * s;  cd1.z = (b0.z - b1.z) * s;
    ca1.w = (b0.w + b1.w) * s;  cd1.w = (b0.w - b1.w) * s;

    long outA0 = base_b + (long)p * row + f4;
    long outA1 = base_b + (long)(p + PQ) * row + f4;
    long dOff  = (long)HALF_L * row;

    out[outA0]        = ca0;
    out[outA0 + dOff] = cd0;
    out[outA1]        = ca1;
    out[outA1 + dOff] = cd1;
}

extern "C" void kernel_launch(void* const* d_in, const int* in_sizes, int n_in,
                              void* d_out, int out_size)
{
    const float4* x = (const float4*)d_in[0];
    float4* out = (float4*)d_out;

    int threads = 256;
    int blocks = TOTAL_T / threads;       // 16384
    haar_dwt_kernel<<<blocks, threads>>>(x, out);
}